// round 15
// baseline (speedup 1.0000x reference)
#include <cuda_runtime.h>
#include <cuda_fp16.h>
#include <cstdint>

// Problem constants
#define BB 4
#define SS 1024
#define DD 1024
#define HH 16
#define DH 64

// ===========================================================================
// Packed fp16 device globals (uint32 = half2 pair along k/dh), all hi-only.
// ===========================================================================
__device__ __align__(16) uint32_t gXh[2097152];                  // x      [4096][512]
__device__ __align__(16) uint32_t gWh[2621440];                  // wq|wk|wv [5120][512]
__device__ __align__(16) uint32_t gWoh[524288];                  // wo     [1024][512]
__device__ __align__(16) uint32_t gAh[2097152];                  // normalized ctx
__device__ __align__(16) uint32_t gQ1h[2097152];
__device__ __align__(16) uint32_t gQ2h[2097152];
__device__ __align__(16) uint32_t gK1h[2097152];
__device__ __align__(16) uint32_t gK2h[2097152];
__device__ __align__(16) uint32_t gVh [2097152];
__device__ float gCtx[4194304];
__device__ float gScaleArr[4096];
__device__ float gBiasArr [4096];
__device__ float gPartS[512], gPartQ[512];

// ===========================================================================
// helpers
// ===========================================================================
static __device__ __forceinline__ uint32_t smem_u32(const void* p) {
    uint32_t a;
    asm("{ .reg .u64 t; cvta.to.shared.u64 t, %1; cvt.u32.u64 %0, t; }"
        : "=r"(a) : "l"(p));
    return a;
}
static __device__ __forceinline__ void ldm_x4(uint32_t* r, uint32_t addr) {
    asm volatile("ldmatrix.sync.aligned.m8n8.x4.shared.b16 {%0,%1,%2,%3}, [%4];"
                 : "=r"(r[0]), "=r"(r[1]), "=r"(r[2]), "=r"(r[3]) : "r"(addr));
}
static __device__ __forceinline__ void ldm_x2(uint32_t* r, uint32_t addr) {
    asm volatile("ldmatrix.sync.aligned.m8n8.x2.shared.b16 {%0,%1}, [%2];"
                 : "=r"(r[0]), "=r"(r[1]) : "r"(addr));
}
static __device__ __forceinline__ void ldm_x4_t(uint32_t* r, uint32_t addr) {
    asm volatile("ldmatrix.sync.aligned.m8n8.x4.trans.shared.b16 {%0,%1,%2,%3}, [%4];"
                 : "=r"(r[0]), "=r"(r[1]), "=r"(r[2]), "=r"(r[3]) : "r"(addr));
}
// fp16 mma, fp32 accumulate
static __device__ __forceinline__ void mma16816(float* c, const uint32_t* a,
                                                const uint32_t* b) {
    asm volatile(
        "mma.sync.aligned.m16n8k16.row.col.f32.f16.f16.f32 "
        "{%0,%1,%2,%3}, {%4,%5,%6,%7}, {%8,%9}, {%0,%1,%2,%3};"
        : "+f"(c[0]), "+f"(c[1]), "+f"(c[2]), "+f"(c[3])
        : "r"(a[0]), "r"(a[1]), "r"(a[2]), "r"(a[3]), "r"(b[0]), "r"(b[1]));
}
static __device__ __forceinline__ uint32_t pack2h(float f0, float f1) {
    __half2 hp; hp.x = __float2half_rn(f0); hp.y = __float2half_rn(f1);
    return *reinterpret_cast<uint32_t*>(&hp);
}
// streaming (evict-first) global access
static __device__ __forceinline__ void stcs(float* p, float v) {
    asm volatile("st.global.cs.f32 [%0], %1;" :: "l"(p), "f"(v) : "memory");
}
static __device__ __forceinline__ float ldcs(const float* p) {
    float v;
    asm volatile("ld.global.cs.f32 %0, [%1];" : "=f"(v) : "l"(p));
    return v;
}
// fast exp on the FMA pipe
static __device__ __forceinline__ float fexp(float x) {
    float t = x * 1.4426950408889634f;
    t = fmaxf(t, -126.0f);
    float fl = floorf(t);
    float f = t - fl;
    float p = 1.33335581e-3f;
    p = fmaf(p, f, 9.61812910e-3f);
    p = fmaf(p, f, 5.55041087e-2f);
    p = fmaf(p, f, 2.40226507e-1f);
    p = fmaf(p, f, 6.93147180e-1f);
    p = fmaf(p, f, 1.0f);
    return p * __int_as_float(((int)fl + 127) << 23);
}
static __device__ __forceinline__ uint32_t sw_off(int row, int chunk) {
    return (uint32_t)(row * 64 + ((chunk ^ ((row >> 1) & 3)) << 4));
}
#define CPA16(dst, src) \
    asm volatile("cp.async.cg.shared.global [%0], [%1], 16;" :: "r"(dst), "l"(src))
#define CPCOMMIT asm volatile("cp.async.commit_group;" ::: "memory")
#define CPWAITG2 asm volatile("cp.async.wait_group 2;" ::: "memory")
#define CPWAIT0  asm volatile("cp.async.wait_group 0;" ::: "memory")

// ===========================================================================
// prep_all: fp32 -> fp16 hi-only conversions.
// ===========================================================================
__global__ void prep_all(const float* __restrict__ x,
                         const float* __restrict__ wq,
                         const float* __restrict__ wk,
                         const float* __restrict__ wv,
                         const float* __restrict__ wo)
{
    int i = blockIdx.x * blockDim.x + threadIdx.x;
    int stride = gridDim.x * blockDim.x;
    for (; i < 5242880; i += stride) {
        const float* src; uint32_t* dh; int j;
        if (i < 2097152)      { j = i;           src = x;  dh = gXh; }
        else if (i < 3145728) { j = i - 2097152; src = wq; dh = gWh; }
        else if (i < 4194304) { j = i - 3145728; src = wk; dh = gWh + 1048576; }
        else if (i < 4718592) { j = i - 4194304; src = wv; dh = gWh + 2097152; }
        else                  { j = i - 4718592; src = wo; dh = gWoh; }
        float2 v = *(const float2*)(src + 2 * (size_t)j);
        dh[j] = pack2h(v.x, v.y);
    }
}

// prep_ctx: gAh = fp16(gCtx * scale + bias)
__global__ void prep_ctx()
{
    int i = blockIdx.x * blockDim.x + threadIdx.x;
    int stride = gridDim.x * blockDim.x;
    for (; i < 2097152; i += stride) {
        int m = i >> 9, kp = i & 511, b = m >> 10;
        float2 v  = *(const float2*)&gCtx[(size_t)m * 1024 + 2 * kp];
        float2 sc = *(const float2*)&gScaleArr[b * 1024 + 2 * kp];
        float2 bi = *(const float2*)&gBiasArr [b * 1024 + 2 * kp];
        gAh[i] = pack2h(v.x * sc.x + bi.x, v.y * sc.y + bi.y);
    }
}

// ===========================================================================
// mma_gemm<MODE>: fp16 1-pass GEMM, 128x128 tile, BK=32,
// 4-stage distance-3 cp.async pipeline. smem: 4 x (A 8K | B 8K) = 64KB.
// (round-13 proven configuration)
// ===========================================================================
template<int MODE>
__global__ __launch_bounds__(256, 2)
void mma_gemm(const float* __restrict__ wqb, const float* __restrict__ wkb,
              const float* __restrict__ wvb, const float* __restrict__ ob,
              float* __restrict__ out)
{
    extern __shared__ char sm[];
    const uint32_t smb = smem_u32(sm);
    const int tid  = threadIdx.x;
    const int lane = tid & 31;
    const int warp = tid >> 5;
    const int wm   = warp >> 1;
    const int wn   = warp & 1;
    const int n0 = blockIdx.x * 128;
    const int m0 = blockIdx.y * 128;
    const int b  = m0 >> 10;

    const uint32_t* Ah = (MODE == 0) ? gXh : gAh;
    const uint32_t* Bh = (MODE == 0) ? gWh : gWoh;
    const float* Wb;
    if (MODE == 0) {
        if (n0 < 2048)      Wb = wqb + n0;
        else if (n0 < 4096) Wb = wkb + (n0 - 2048);
        else                Wb = wvb + (n0 - 4096);
    } else {
        Wb = ob + n0;
    }

    float acc[2][8][4];
#pragma unroll
    for (int i = 0; i < 2; i++)
#pragma unroll
        for (int j = 0; j < 8; j++)
#pragma unroll
            for (int v = 0; v < 4; v++) acc[i][j][v] = 0.f;

#define STAGE_GEMM(c, buf)                                                        \
    {                                                                             \
        _Pragma("unroll")                                                         \
        for (int i = 0; i < 4; i++) {                                             \
            int t = tid + i * 256;                                                \
            int tile = t >> 9;                                                    \
            int r = (t >> 2) & 127;                                               \
            int u = t & 3;                                                        \
            uint32_t dst = smb + (uint32_t)(buf) * 16384u + tile * 8192u          \
                           + sw_off(r, u);                                        \
            const uint32_t* sa = (tile == 0) ? Ah : Bh;                           \
            const uint32_t* src = sa + (size_t)((tile == 0 ? m0 : n0) + r) * 512  \
                                   + (c) * 16 + u * 4;                            \
            CPA16(dst, src);                                                      \
        }                                                                         \
        CPCOMMIT;                                                                 \
    }

    STAGE_GEMM(0, 0);
    STAGE_GEMM(1, 1);
    STAGE_GEMM(2, 2);
    for (int c = 0; c < 32; c++) {
        if (c < 29) { CPWAITG2; } else { CPWAIT0; }
        __syncthreads();
        if (c < 29) STAGE_GEMM(c + 3, (c + 3) & 3);

        const uint32_t base = smb + (uint32_t)(c & 3) * 16384u;
        const uint32_t AhU = base;
        const uint32_t BhiU = base + 8192u;
#pragma unroll
        for (int kk = 0; kk < 2; kk++) {
            uint32_t ah[2][4];
            const int arow = wm * 32 + (lane & 7) + (((lane >> 3) & 1) << 3);
            const int achunk = kk * 2 + (lane >> 4);
#pragma unroll
            for (int mi = 0; mi < 2; mi++)
                ldm_x4(ah[mi], AhU + sw_off(arow + mi * 16, achunk));
            const int brow0 = wn * 64 + (lane & 7) + ((lane >> 4) << 3);
            const int bchunk = kk * 2 + ((lane >> 3) & 1);
#pragma unroll
            for (int half = 0; half < 2; half++) {
                uint32_t bhf[2][4];
#pragma unroll
                for (int j = 0; j < 2; j++)
                    ldm_x4(bhf[j], BhiU + sw_off(brow0 + half * 32 + j * 16, bchunk));
#pragma unroll
                for (int mi = 0; mi < 2; mi++)
#pragma unroll
                    for (int j = 0; j < 2; j++)
#pragma unroll
                        for (int s = 0; s < 2; s++)
                            mma16816(acc[mi][half * 4 + j * 2 + s],
                                     ah[mi], &bhf[j][s * 2]);
            }
        }
    }
#undef STAGE_GEMM

    if (MODE == 0) {
        const int sect = n0 >> 10;
        uint32_t* dstH = (sect == 0) ? gQ1h : (sect == 1) ? gQ2h :
                         (sect == 2) ? gK1h : (sect == 3) ? gK2h : gVh;
#pragma unroll
        for (int mi = 0; mi < 2; mi++) {
            int m = m0 + wm * 32 + mi * 16 + (lane >> 2);
            int s = m & 1023;
#pragma unroll
            for (int nh = 0; nh < 8; nh++) {
                int nl = wn * 64 + nh * 8 + 2 * (lane & 3);
                int nn = (n0 & 1023) + nl;
                int h = nn >> 6, dh = nn & 63;
                float b0 = Wb[nl], b1 = Wb[nl + 1];
                size_t base = ((size_t)((b << 4) + h) * 1024 + s) * 32 + (dh >> 1);
                dstH[base]       = pack2h(acc[mi][nh][0] + b0, acc[mi][nh][1] + b1);
                dstH[base + 256] = pack2h(acc[mi][nh][2] + b0, acc[mi][nh][3] + b1);
            }
        }
    } else {
#pragma unroll
        for (int mi = 0; mi < 2; mi++) {
            int m = m0 + wm * 32 + mi * 16 + (lane >> 2);
#pragma unroll
            for (int nh = 0; nh < 8; nh++) {
                int nl = wn * 64 + nh * 8 + 2 * (lane & 3);
                float b0 = Wb[nl], b1 = Wb[nl + 1];
                float2 v0; v0.x = acc[mi][nh][0] + b0; v0.y = acc[mi][nh][1] + b1;
                float2 v1; v1.x = acc[mi][nh][2] + b0; v1.y = acc[mi][nh][3] + b1;
                *(float2*)&out[(size_t)m * 1024 + n0 + nl]       = v0;
                *(float2*)&out[(size_t)(m + 8) * 1024 + n0 + nl] = v1;
            }
        }
    }
}

// ===========================================================================
// attn_kernel: qt=16, 256 thr, occ 2. K/V hi-only, distance-3 pipelines.
// (round-13 proven configuration + streaming cache hints)
// smem: S fp32[16][1032] (66048) | KV 4x8KB (32768) | Pc 2x2KB (4096)
// ===========================================================================
#define SD 1032
#define OFF_KV 66048u
#define OFF_PC 98816u
#define ATTN_SMEM 102912

static __device__ __forceinline__ void stage_kv(uint32_t smb, const uint32_t* sH,
                                                int bh, int ch64, int buf, int tid)
{
#pragma unroll
    for (int i = 0; i < 2; i++) {
        int t = tid + i * 256;            // 0..511
        int row = t >> 3;                 // 0..63
        int cu = t & 7;
        uint32_t dst = smb + OFF_KV + buf * 8192u +
                       row * 128u + (uint32_t)((cu ^ (row & 7)) << 4);
        const uint32_t* src = sH + ((size_t)bh * 1024 + ch64 * 64 + row) * 32 + cu * 4;
        CPA16(dst, src);
    }
    CPCOMMIT;
}

__global__ __launch_bounds__(256, 2)
void attn_kernel(const float* __restrict__ Cmask,
                 const int*   __restrict__ pad,
                 const float* __restrict__ lamp,
                 float* __restrict__ attn1,
                 float* __restrict__ attn2)
{
    extern __shared__ char smc[];
    const uint32_t smb = smem_u32(smc);
    float* S = (float*)smc;

    const int qt = blockIdx.x;
    const int h  = blockIdx.y;
    const int b  = blockIdx.z;
    const int tid  = threadIdx.x;
    const int wid  = tid >> 5;
    const int lane = tid & 31;
    const int bh = b * 16 + h;
    const int qbase = qt * 16;
    const int r  = lane >> 2;
    const int c2 = (lane & 3) * 2;
    const int* padrow = pad + b * 1024;

#define SCORE_PASS(KH, QH)                                                       \
    {                                                                            \
        uint32_t qh[4][4];                                                       \
        {                                                                        \
            size_t qb0 = ((size_t)bh * 1024 + qbase + r) * 32;                   \
            size_t qb1 = qb0 + 8 * 32;                                           \
            _Pragma("unroll")                                                    \
            for (int kk = 0; kk < 4; kk++) {                                     \
                int p = kk * 8 + (lane & 3);                                     \
                qh[kk][0] = QH[qb0 + p];                                         \
                qh[kk][1] = QH[qb1 + p];                                         \
                qh[kk][2] = QH[qb0 + p + 4];                                     \
                qh[kk][3] = QH[qb1 + p + 4];                                     \
            }                                                                    \
        }                                                                        \
        for (int ch = 0; ch < 16; ch++) {                                        \
            if (ch < 13) { CPWAITG2; } else { CPWAIT0; }                         \
            __syncthreads();                                                     \
            if (ch < 13) stage_kv(smb, KH, bh, ch + 3, (ch + 3) & 3, tid);       \
            const uint32_t KU = smb + OFF_KV + (uint32_t)(ch & 3) * 8192u;       \
            float c0[4] = {0.f, 0.f, 0.f, 0.f};                                  \
            const int brow = wid * 8 + (lane & 7);                               \
            _Pragma("unroll")                                                    \
            for (int kk = 0; kk < 4; kk++) {                                     \
                int bch = kk * 2 + ((lane >> 3) & 1);                            \
                uint32_t off = brow * 128 + ((bch ^ (brow & 7)) << 4);           \
                uint32_t bhf[2];                                                 \
                ldm_x2(bhf, KU + off);                                           \
                mma16816(c0, qh[kk], bhf);                                       \
            }                                                                    \
            const int col = ch * 64 + wid * 8 + c2;                              \
            float2 v;                                                            \
            v.x = c0[0] * 0.125f; v.y = c0[1] * 0.125f;                          \
            *(float2*)&S[r * SD + col] = v;                                      \
            v.x = c0[2] * 0.125f; v.y = c0[3] * 0.125f;                          \
            *(float2*)&S[(r + 8) * SD + col] = v;                                \
        }                                                                        \
    }

    // ---------------- variant 2 scores -> softmax -> attn2 ----------------
    stage_kv(smb, gK2h, bh, 0, 0, tid);
    stage_kv(smb, gK2h, bh, 1, 1, tid);
    stage_kv(smb, gK2h, bh, 2, 2, tid);
    SCORE_PASS(gK2h, gQ2h);

    stage_kv(smb, gK1h, bh, 0, 0, tid);
    stage_kv(smb, gK1h, bh, 1, 1, tid);
    stage_kv(smb, gK1h, bh, 2, 2, tid);
    __syncthreads();

    for (int q = wid; q < 16; q += 8) {
        float* row = S + q * SD;
        float vreg[32];
        float m = -3.4e38f;
#pragma unroll
        for (int j = 0; j < 32; j++) {
            int k = lane + 32 * j;
            float v = row[k];
            if (padrow[k] == 0) v = -1e9f;
            vreg[j] = v;
            m = fmaxf(m, v);
        }
#pragma unroll
        for (int o = 16; o > 0; o >>= 1) m = fmaxf(m, __shfl_xor_sync(0xffffffffu, m, o));
        float s = 0.f;
#pragma unroll
        for (int j = 0; j < 32; j++) { vreg[j] = fexp(vreg[j] - m); s += vreg[j]; }
#pragma unroll
        for (int o = 16; o > 0; o >>= 1) s += __shfl_xor_sync(0xffffffffu, s, o);
        float rr = 1.0f / s;
        float* gout = attn2 + ((size_t)bh * 1024 + qbase + q) * 1024;
#pragma unroll
        for (int j = 0; j < 32; j++)
            gout[lane + 32 * j] = vreg[j] * rr;
    }
    __syncthreads();

    // ---------------- variant 1 scores -> softmax+combine -> attn1 & P in S -
    SCORE_PASS(gK1h, gQ1h);

    stage_kv(smb, gVh, bh, 0, 0, tid);
    stage_kv(smb, gVh, bh, 1, 1, tid);
    stage_kv(smb, gVh, bh, 2, 2, tid);
    __syncthreads();

    {
        const float lam = lamp[0];
        for (int q = wid; q < 16; q += 8) {
            float* row = S + q * SD;
            float vreg[32];
            float m = -3.4e38f;
#pragma unroll
            for (int j = 0; j < 32; j++) {
                int k = lane + 32 * j;
                float v = row[k];
                if (padrow[k] == 0) v = -1e9f;
                vreg[j] = v;
                m = fmaxf(m, v);
            }
#pragma unroll
            for (int o = 16; o > 0; o >>= 1) m = fmaxf(m, __shfl_xor_sync(0xffffffffu, m, o));
            float s = 0.f;
#pragma unroll
            for (int j = 0; j < 32; j++) { vreg[j] = fexp(vreg[j] - m); s += vreg[j]; }
#pragma unroll
            for (int o = 16; o > 0; o >>= 1) s += __shfl_xor_sync(0xffffffffu, s, o);
            float rr = 1.0f / s;
            float* gout = attn1 + ((size_t)bh * 1024 + qbase + q) * 1024;
            const float* a2g = attn2 + ((size_t)bh * 1024 + qbase + q) * 1024;
            const float* cg  = Cmask + ((size_t)b * 1024 + qbase + q) * 1024;
            // attn1 write: streaming (never re-read); Cmask read: streaming.
#pragma unroll
            for (int j = 0; j < 32; j++) {
                int k = lane + 32 * j;
                float e = vreg[j] * rr;
                stcs(&gout[k], e);
                row[k] = ldcs(&cg[k]) * (e - lam * a2g[k]);
            }
        }
    }
    __syncthreads();

    // ---------------- phase 2: ctx = P @ V, distance-3 ---------------------
    {
        const uint32_t ua = (uint32_t)((((lane & 15) * 2 +
                             ((lane >> 4) ^ (((lane & 15) >> 2) & 1)))) << 4);
        float cacc[4] = {0.f, 0.f, 0.f, 0.f};
        for (int ch = 0; ch < 16; ch++) {
            {
                uint32_t* Pchi = (uint32_t*)(smc + OFF_PC + (ch & 1) * 2048u);
#pragma unroll
                for (int i = 0; i < 2; i++) {
                    int pidx = tid + i * 256;
                    int q  = pidx >> 5;
                    int kp = pidx & 31;
                    int kl = kp * 2;
                    uint32_t hv = pack2h(S[q * SD + ch * 64 + kl],
                                         S[q * SD + ch * 64 + kl + 1]);
                    int kb16  = kl >> 4;
                    int colin = kl & 15;
                    int half  = colin >> 3;
                    int w     = (colin & 7) >> 1;
                    int u     = q * 2 + (half ^ ((q >> 2) & 1));
                    Pchi[kb16 * 128 + u * 4 + w] = hv;
                }
            }
            if (ch < 13) { CPWAITG2; } else { CPWAIT0; }
            __syncthreads();
            if (ch < 13) stage_kv(smb, gVh, bh, ch + 3, (ch + 3) & 3, tid);

            const uint32_t VU  = smb + OFF_KV + (uint32_t)(ch & 3) * 8192u;
            const uint32_t PbU = smb + OFF_PC + (uint32_t)(ch & 1) * 2048u;
#pragma unroll
            for (int k2 = 0; k2 < 2; k2++) {
                int lrow = k2 * 32 + (lane >> 3) * 8 + (lane & 7);
                uint32_t boff = lrow * 128 + ((wid ^ (lrow & 7)) << 4);
                uint32_t bhf[4];
                ldm_x4_t(bhf, VU + boff);
#pragma unroll
                for (int sub = 0; sub < 2; sub++) {
                    int kb16 = k2 * 2 + sub;
                    uint32_t ah[4];
                    ldm_x4(ah, PbU + kb16 * 512 + ua);
                    mma16816(cacc, ah, &bhf[sub * 2]);
                }
            }
        }
        size_t base = ((size_t)(b * 1024 + qbase + r)) * 1024 + h * 64 + wid * 8 + c2;
        float2 v0; v0.x = cacc[0]; v0.y = cacc[1];
        float2 v1; v1.x = cacc[2]; v1.y = cacc[3];
        *(float2*)&gCtx[base]            = v0;
        *(float2*)&gCtx[base + 8 * 1024] = v1;
    }
#undef SCORE_PASS
}

// ---------------------------------------------------------------------------
// stats: two-stage GroupNorm stats -> folded per-(b,d) scale/bias
// ---------------------------------------------------------------------------
__global__ void stats_part(void)
{
    const int idx = blockIdx.x;          // 0..511
    const int bh = idx >> 3, eighth = idx & 7;
    const int b = bh >> 4, h = bh & 15;
    const int tid = threadIdx.x;
    __shared__ float rs[256], rq[256];
    float s = 0.f, sq = 0.f;
    for (int t = tid; t < 8192; t += 256) {
        int srow = eighth * 128 + (t >> 6), d = t & 63;
        float x = gCtx[((size_t)b * 1024 + srow) * 1024 + h * 64 + d];
        s += x; sq += x * x;
    }
    rs[tid] = s; rq[tid] = sq;
    __syncthreads();
    for (int o = 128; o > 0; o >>= 1) {
        if (tid < o) { rs[tid] += rs[tid + o]; rq[tid] += rq[tid + o]; }
        __syncthreads();
    }
    if (tid == 0) { gPartS[idx] = rs[0]; gPartQ[idx] = rq[0]; }
}

__global__ void stats_fin(const float* __restrict__ gnw,
                          const float* __restrict__ gnb)
{
    const int bh = blockIdx.x;
    const int b = bh >> 4, h = bh & 15;
    const int d0 = threadIdx.x;          // 0..63
    float s = 0.f, sq = 0.f;
#pragma unroll
    for (int i = 0; i < 8; i++) { s += gPartS[bh * 8 + i]; sq += gPartQ[bh * 8 + i]; }
    float mean = s * (1.0f / 65536.0f);
    float var  = sq * (1.0f / 65536.0f) - mean * mean;
    float rstd = rsqrtf(var + 1e-5f);
    int d = h * 64 + d0;
    float w = gnw[d];
    gScaleArr[b * 1024 + d] = rstd * w * 0.19999999999999996f;
    gBiasArr [b * 1024 + d] = (gnb[d] - mean * rstd * w) * 0.19999999999999996f;
}

// ---------------------------------------------------------------------------
// Launch
// ---------------------------------------------------------------------------
extern "C" void kernel_launch(void* const* d_in, const int* in_sizes, int n_in,
                              void* d_out, int out_size)
{
    const float* x    = (const float*)d_in[0];
    const float* lam  = (const float*)d_in[1];
    const float* C    = (const float*)d_in[2];
    const int*   pad  = (const int*)  d_in[3];
    const float* wq   = (const float*)d_in[4];
    const float* wqb  = (const float*)d_in[5];
    const float* wk   = (const float*)d_in[6];
    const float* wkb  = (const float*)d_in[7];
    const float* wv   = (const float*)d_in[8];
    const float* wvb  = (const float*)d_in[9];
    const float* wo   = (const float*)d_in[10];
    const float* wob  = (const float*)d_in[11];
    const float* gnw  = (const float*)d_in[12];
    const float* gnb  = (const float*)d_in[13];

    float* out   = (float*)d_out;
    float* attn1 = out + (size_t)BB * SS * DD;
    float* attn2 = attn1 + (size_t)BB * HH * SS * SS;

    cudaFuncSetAttribute(attn_kernel, cudaFuncAttributeMaxDynamicSharedMemorySize,
                         ATTN_SMEM);
    cudaFuncSetAttribute(mma_gemm<0>, cudaFuncAttributeMaxDynamicSharedMemorySize, 65536);
    cudaFuncSetAttribute(mma_gemm<1>, cudaFuncAttributeMaxDynamicSharedMemorySize, 65536);

    prep_all<<<512, 256>>>(x, wq, wk, wv, wo);
    mma_gemm<0><<<dim3(40, 32), 256, 65536>>>(wqb, wkb, wvb, nullptr, nullptr);
    attn_kernel<<<dim3(64, 16, 4), 256, ATTN_SMEM>>>(C, pad, lam, attn1, attn2);
    stats_part<<<512, 256>>>();
    stats_fin<<<64, 64>>>(gnw, gnb);
    prep_ctx<<<512, 256>>>();
    mma_gemm<1><<<dim3(8, 32), 256, 65536>>>(nullptr, nullptr, nullptr, wob, out);
}

// round 16
// speedup vs baseline: 1.0360x; 1.0360x over previous
#include <cuda_runtime.h>
#include <cuda_fp16.h>
#include <cstdint>

// Problem constants
#define BB 4
#define SS 1024
#define DD 1024
#define HH 16
#define DH 64

// ===========================================================================
// Packed fp16 device globals (uint32 = half2 pair along k/dh), all hi-only.
// ===========================================================================
__device__ __align__(16) uint32_t gXh[2097152];                  // x      [4096][512]
__device__ __align__(16) uint32_t gWh[2621440];                  // wq|wk|wv [5120][512]
__device__ __align__(16) uint32_t gWoh[524288];                  // wo     [1024][512]
__device__ __align__(16) uint32_t gAh[2097152];                  // normalized ctx
__device__ __align__(16) uint32_t gQ1h[2097152];
__device__ __align__(16) uint32_t gQ2h[2097152];
__device__ __align__(16) uint32_t gK1h[2097152];
__device__ __align__(16) uint32_t gK2h[2097152];
__device__ __align__(16) uint32_t gVh [2097152];
__device__ float gCtx[4194304];
__device__ float gScaleArr[4096];
__device__ float gBiasArr [4096];
__device__ float gPartS[512], gPartQ[512];

// ===========================================================================
// helpers
// ===========================================================================
static __device__ __forceinline__ uint32_t smem_u32(const void* p) {
    uint32_t a;
    asm("{ .reg .u64 t; cvta.to.shared.u64 t, %1; cvt.u32.u64 %0, t; }"
        : "=r"(a) : "l"(p));
    return a;
}
static __device__ __forceinline__ void ldm_x4(uint32_t* r, uint32_t addr) {
    asm volatile("ldmatrix.sync.aligned.m8n8.x4.shared.b16 {%0,%1,%2,%3}, [%4];"
                 : "=r"(r[0]), "=r"(r[1]), "=r"(r[2]), "=r"(r[3]) : "r"(addr));
}
static __device__ __forceinline__ void ldm_x2(uint32_t* r, uint32_t addr) {
    asm volatile("ldmatrix.sync.aligned.m8n8.x2.shared.b16 {%0,%1}, [%2];"
                 : "=r"(r[0]), "=r"(r[1]) : "r"(addr));
}
static __device__ __forceinline__ void ldm_x4_t(uint32_t* r, uint32_t addr) {
    asm volatile("ldmatrix.sync.aligned.m8n8.x4.trans.shared.b16 {%0,%1,%2,%3}, [%4];"
                 : "=r"(r[0]), "=r"(r[1]), "=r"(r[2]), "=r"(r[3]) : "r"(addr));
}
// fp16 mma, fp32 accumulate
static __device__ __forceinline__ void mma16816(float* c, const uint32_t* a,
                                                const uint32_t* b) {
    asm volatile(
        "mma.sync.aligned.m16n8k16.row.col.f32.f16.f16.f32 "
        "{%0,%1,%2,%3}, {%4,%5,%6,%7}, {%8,%9}, {%0,%1,%2,%3};"
        : "+f"(c[0]), "+f"(c[1]), "+f"(c[2]), "+f"(c[3])
        : "r"(a[0]), "r"(a[1]), "r"(a[2]), "r"(a[3]), "r"(b[0]), "r"(b[1]));
}
static __device__ __forceinline__ uint32_t pack2h(float f0, float f1) {
    __half2 hp; hp.x = __float2half_rn(f0); hp.y = __float2half_rn(f1);
    return *reinterpret_cast<uint32_t*>(&hp);
}
// fast exp on the FMA pipe
static __device__ __forceinline__ float fexp(float x) {
    float t = x * 1.4426950408889634f;
    t = fmaxf(t, -126.0f);
    float fl = floorf(t);
    float f = t - fl;
    float p = 1.33335581e-3f;
    p = fmaf(p, f, 9.61812910e-3f);
    p = fmaf(p, f, 5.55041087e-2f);
    p = fmaf(p, f, 2.40226507e-1f);
    p = fmaf(p, f, 6.93147180e-1f);
    p = fmaf(p, f, 1.0f);
    return p * __int_as_float(((int)fl + 127) << 23);
}
static __device__ __forceinline__ uint32_t sw_off(int row, int chunk) {
    return (uint32_t)(row * 64 + ((chunk ^ ((row >> 1) & 3)) << 4));
}
#define CPA16(dst, src) \
    asm volatile("cp.async.cg.shared.global [%0], [%1], 16;" :: "r"(dst), "l"(src))
#define CPCOMMIT asm volatile("cp.async.commit_group;" ::: "memory")
#define CPWAITG2 asm volatile("cp.async.wait_group 2;" ::: "memory")
#define CPWAIT0  asm volatile("cp.async.wait_group 0;" ::: "memory")

// ===========================================================================
// prep_all: fp32 -> fp16 hi-only conversions.
// ===========================================================================
__global__ void prep_all(const float* __restrict__ x,
                         const float* __restrict__ wq,
                         const float* __restrict__ wk,
                         const float* __restrict__ wv,
                         const float* __restrict__ wo)
{
    int i = blockIdx.x * blockDim.x + threadIdx.x;
    int stride = gridDim.x * blockDim.x;
    for (; i < 5242880; i += stride) {
        const float* src; uint32_t* dh; int j;
        if (i < 2097152)      { j = i;           src = x;  dh = gXh; }
        else if (i < 3145728) { j = i - 2097152; src = wq; dh = gWh; }
        else if (i < 4194304) { j = i - 3145728; src = wk; dh = gWh + 1048576; }
        else if (i < 4718592) { j = i - 4194304; src = wv; dh = gWh + 2097152; }
        else                  { j = i - 4718592; src = wo; dh = gWoh; }
        float2 v = *(const float2*)(src + 2 * (size_t)j);
        dh[j] = pack2h(v.x, v.y);
    }
}

// prep_ctx: gAh = fp16(gCtx * scale + bias)
__global__ void prep_ctx()
{
    int i = blockIdx.x * blockDim.x + threadIdx.x;
    int stride = gridDim.x * blockDim.x;
    for (; i < 2097152; i += stride) {
        int m = i >> 9, kp = i & 511, b = m >> 10;
        float2 v  = *(const float2*)&gCtx[(size_t)m * 1024 + 2 * kp];
        float2 sc = *(const float2*)&gScaleArr[b * 1024 + 2 * kp];
        float2 bi = *(const float2*)&gBiasArr [b * 1024 + 2 * kp];
        gAh[i] = pack2h(v.x * sc.x + bi.x, v.y * sc.y + bi.y);
    }
}

// ===========================================================================
// mma_gemm<MODE>: fp16 1-pass GEMM, 128x128 tile, BK=32,
// 4-stage distance-3 cp.async pipeline. smem: 4 x (A 8K | B 8K) = 64KB.
// (round-13 proven configuration)
// ===========================================================================
template<int MODE>
__global__ __launch_bounds__(256, 2)
void mma_gemm(const float* __restrict__ wqb, const float* __restrict__ wkb,
              const float* __restrict__ wvb, const float* __restrict__ ob,
              float* __restrict__ out)
{
    extern __shared__ char sm[];
    const uint32_t smb = smem_u32(sm);
    const int tid  = threadIdx.x;
    const int lane = tid & 31;
    const int warp = tid >> 5;
    const int wm   = warp >> 1;
    const int wn   = warp & 1;
    const int n0 = blockIdx.x * 128;
    const int m0 = blockIdx.y * 128;
    const int b  = m0 >> 10;

    const uint32_t* Ah = (MODE == 0) ? gXh : gAh;
    const uint32_t* Bh = (MODE == 0) ? gWh : gWoh;
    const float* Wb;
    if (MODE == 0) {
        if (n0 < 2048)      Wb = wqb + n0;
        else if (n0 < 4096) Wb = wkb + (n0 - 2048);
        else                Wb = wvb + (n0 - 4096);
    } else {
        Wb = ob + n0;
    }

    float acc[2][8][4];
#pragma unroll
    for (int i = 0; i < 2; i++)
#pragma unroll
        for (int j = 0; j < 8; j++)
#pragma unroll
            for (int v = 0; v < 4; v++) acc[i][j][v] = 0.f;

#define STAGE_GEMM(c, buf)                                                        \
    {                                                                             \
        _Pragma("unroll")                                                         \
        for (int i = 0; i < 4; i++) {                                             \
            int t = tid + i * 256;                                                \
            int tile = t >> 9;                                                    \
            int r = (t >> 2) & 127;                                               \
            int u = t & 3;                                                        \
            uint32_t dst = smb + (uint32_t)(buf) * 16384u + tile * 8192u          \
                           + sw_off(r, u);                                        \
            const uint32_t* sa = (tile == 0) ? Ah : Bh;                           \
            const uint32_t* src = sa + (size_t)((tile == 0 ? m0 : n0) + r) * 512  \
                                   + (c) * 16 + u * 4;                            \
            CPA16(dst, src);                                                      \
        }                                                                         \
        CPCOMMIT;                                                                 \
    }

    STAGE_GEMM(0, 0);
    STAGE_GEMM(1, 1);
    STAGE_GEMM(2, 2);
    for (int c = 0; c < 32; c++) {
        if (c < 29) { CPWAITG2; } else { CPWAIT0; }
        __syncthreads();
        if (c < 29) STAGE_GEMM(c + 3, (c + 3) & 3);

        const uint32_t base = smb + (uint32_t)(c & 3) * 16384u;
        const uint32_t AhU = base;
        const uint32_t BhiU = base + 8192u;
#pragma unroll
        for (int kk = 0; kk < 2; kk++) {
            uint32_t ah[2][4];
            const int arow = wm * 32 + (lane & 7) + (((lane >> 3) & 1) << 3);
            const int achunk = kk * 2 + (lane >> 4);
#pragma unroll
            for (int mi = 0; mi < 2; mi++)
                ldm_x4(ah[mi], AhU + sw_off(arow + mi * 16, achunk));
            const int brow0 = wn * 64 + (lane & 7) + ((lane >> 4) << 3);
            const int bchunk = kk * 2 + ((lane >> 3) & 1);
#pragma unroll
            for (int half = 0; half < 2; half++) {
                uint32_t bhf[2][4];
#pragma unroll
                for (int j = 0; j < 2; j++)
                    ldm_x4(bhf[j], BhiU + sw_off(brow0 + half * 32 + j * 16, bchunk));
#pragma unroll
                for (int mi = 0; mi < 2; mi++)
#pragma unroll
                    for (int j = 0; j < 2; j++)
#pragma unroll
                        for (int s = 0; s < 2; s++)
                            mma16816(acc[mi][half * 4 + j * 2 + s],
                                     ah[mi], &bhf[j][s * 2]);
            }
        }
    }
#undef STAGE_GEMM

    if (MODE == 0) {
        const int sect = n0 >> 10;
        uint32_t* dstH = (sect == 0) ? gQ1h : (sect == 1) ? gQ2h :
                         (sect == 2) ? gK1h : (sect == 3) ? gK2h : gVh;
#pragma unroll
        for (int mi = 0; mi < 2; mi++) {
            int m = m0 + wm * 32 + mi * 16 + (lane >> 2);
            int s = m & 1023;
#pragma unroll
            for (int nh = 0; nh < 8; nh++) {
                int nl = wn * 64 + nh * 8 + 2 * (lane & 3);
                int nn = (n0 & 1023) + nl;
                int h = nn >> 6, dh = nn & 63;
                float b0 = Wb[nl], b1 = Wb[nl + 1];
                size_t base = ((size_t)((b << 4) + h) * 1024 + s) * 32 + (dh >> 1);
                dstH[base]       = pack2h(acc[mi][nh][0] + b0, acc[mi][nh][1] + b1);
                dstH[base + 256] = pack2h(acc[mi][nh][2] + b0, acc[mi][nh][3] + b1);
            }
        }
    } else {
#pragma unroll
        for (int mi = 0; mi < 2; mi++) {
            int m = m0 + wm * 32 + mi * 16 + (lane >> 2);
#pragma unroll
            for (int nh = 0; nh < 8; nh++) {
                int nl = wn * 64 + nh * 8 + 2 * (lane & 3);
                float b0 = Wb[nl], b1 = Wb[nl + 1];
                float2 v0; v0.x = acc[mi][nh][0] + b0; v0.y = acc[mi][nh][1] + b1;
                float2 v1; v1.x = acc[mi][nh][2] + b0; v1.y = acc[mi][nh][3] + b1;
                *(float2*)&out[(size_t)m * 1024 + n0 + nl]       = v0;
                *(float2*)&out[(size_t)(m + 8) * 1024 + n0 + nl] = v1;
            }
        }
    }
}

// ===========================================================================
// attn_kernel: qt=16, 256 thr, occ 2. K/V hi-only, distance-3 pipelines.
// (round-13 proven configuration, unchanged)
// smem: S fp32[16][1032] (66048) | KV 4x8KB (32768) | Pc 2x2KB (4096)
// ===========================================================================
#define SD 1032
#define OFF_KV 66048u
#define OFF_PC 98816u
#define ATTN_SMEM 102912

static __device__ __forceinline__ void stage_kv(uint32_t smb, const uint32_t* sH,
                                                int bh, int ch64, int buf, int tid)
{
#pragma unroll
    for (int i = 0; i < 2; i++) {
        int t = tid + i * 256;            // 0..511
        int row = t >> 3;                 // 0..63
        int cu = t & 7;
        uint32_t dst = smb + OFF_KV + buf * 8192u +
                       row * 128u + (uint32_t)((cu ^ (row & 7)) << 4);
        const uint32_t* src = sH + ((size_t)bh * 1024 + ch64 * 64 + row) * 32 + cu * 4;
        CPA16(dst, src);
    }
    CPCOMMIT;
}

__global__ __launch_bounds__(256, 2)
void attn_kernel(const float* __restrict__ Cmask,
                 const int*   __restrict__ pad,
                 const float* __restrict__ lamp,
                 float* __restrict__ attn1,
                 float* __restrict__ attn2)
{
    extern __shared__ char smc[];
    const uint32_t smb = smem_u32(smc);
    float* S = (float*)smc;

    const int qt = blockIdx.x;
    const int h  = blockIdx.y;
    const int b  = blockIdx.z;
    const int tid  = threadIdx.x;
    const int wid  = tid >> 5;
    const int lane = tid & 31;
    const int bh = b * 16 + h;
    const int qbase = qt * 16;
    const int r  = lane >> 2;
    const int c2 = (lane & 3) * 2;
    const int* padrow = pad + b * 1024;

#define SCORE_PASS(KH, QH)                                                       \
    {                                                                            \
        uint32_t qh[4][4];                                                       \
        {                                                                        \
            size_t qb0 = ((size_t)bh * 1024 + qbase + r) * 32;                   \
            size_t qb1 = qb0 + 8 * 32;                                           \
            _Pragma("unroll")                                                    \
            for (int kk = 0; kk < 4; kk++) {                                     \
                int p = kk * 8 + (lane & 3);                                     \
                qh[kk][0] = QH[qb0 + p];                                         \
                qh[kk][1] = QH[qb1 + p];                                         \
                qh[kk][2] = QH[qb0 + p + 4];                                     \
                qh[kk][3] = QH[qb1 + p + 4];                                     \
            }                                                                    \
        }                                                                        \
        for (int ch = 0; ch < 16; ch++) {                                        \
            if (ch < 13) { CPWAITG2; } else { CPWAIT0; }                         \
            __syncthreads();                                                     \
            if (ch < 13) stage_kv(smb, KH, bh, ch + 3, (ch + 3) & 3, tid);       \
            const uint32_t KU = smb + OFF_KV + (uint32_t)(ch & 3) * 8192u;       \
            float c0[4] = {0.f, 0.f, 0.f, 0.f};                                  \
            const int brow = wid * 8 + (lane & 7);                               \
            _Pragma("unroll")                                                    \
            for (int kk = 0; kk < 4; kk++) {                                     \
                int bch = kk * 2 + ((lane >> 3) & 1);                            \
                uint32_t off = brow * 128 + ((bch ^ (brow & 7)) << 4);           \
                uint32_t bhf[2];                                                 \
                ldm_x2(bhf, KU + off);                                           \
                mma16816(c0, qh[kk], bhf);                                       \
            }                                                                    \
            const int col = ch * 64 + wid * 8 + c2;                              \
            float2 v;                                                            \
            v.x = c0[0] * 0.125f; v.y = c0[1] * 0.125f;                          \
            *(float2*)&S[r * SD + col] = v;                                      \
            v.x = c0[2] * 0.125f; v.y = c0[3] * 0.125f;                          \
            *(float2*)&S[(r + 8) * SD + col] = v;                                \
        }                                                                        \
    }

    // ---------------- variant 2 scores -> softmax -> attn2 ----------------
    stage_kv(smb, gK2h, bh, 0, 0, tid);
    stage_kv(smb, gK2h, bh, 1, 1, tid);
    stage_kv(smb, gK2h, bh, 2, 2, tid);
    SCORE_PASS(gK2h, gQ2h);

    stage_kv(smb, gK1h, bh, 0, 0, tid);
    stage_kv(smb, gK1h, bh, 1, 1, tid);
    stage_kv(smb, gK1h, bh, 2, 2, tid);
    __syncthreads();

    for (int q = wid; q < 16; q += 8) {
        float* row = S + q * SD;
        float vreg[32];
        float m = -3.4e38f;
#pragma unroll
        for (int j = 0; j < 32; j++) {
            int k = lane + 32 * j;
            float v = row[k];
            if (padrow[k] == 0) v = -1e9f;
            vreg[j] = v;
            m = fmaxf(m, v);
        }
#pragma unroll
        for (int o = 16; o > 0; o >>= 1) m = fmaxf(m, __shfl_xor_sync(0xffffffffu, m, o));
        float s = 0.f;
#pragma unroll
        for (int j = 0; j < 32; j++) { vreg[j] = fexp(vreg[j] - m); s += vreg[j]; }
#pragma unroll
        for (int o = 16; o > 0; o >>= 1) s += __shfl_xor_sync(0xffffffffu, s, o);
        float rr = 1.0f / s;
        float* gout = attn2 + ((size_t)bh * 1024 + qbase + q) * 1024;
#pragma unroll
        for (int j = 0; j < 32; j++)
            gout[lane + 32 * j] = vreg[j] * rr;
    }
    __syncthreads();

    // ---------------- variant 1 scores -> softmax+combine -> attn1 & P in S -
    SCORE_PASS(gK1h, gQ1h);

    stage_kv(smb, gVh, bh, 0, 0, tid);
    stage_kv(smb, gVh, bh, 1, 1, tid);
    stage_kv(smb, gVh, bh, 2, 2, tid);
    __syncthreads();

    {
        const float lam = lamp[0];
        for (int q = wid; q < 16; q += 8) {
            float* row = S + q * SD;
            float vreg[32];
            float m = -3.4e38f;
#pragma unroll
            for (int j = 0; j < 32; j++) {
                int k = lane + 32 * j;
                float v = row[k];
                if (padrow[k] == 0) v = -1e9f;
                vreg[j] = v;
                m = fmaxf(m, v);
            }
#pragma unroll
            for (int o = 16; o > 0; o >>= 1) m = fmaxf(m, __shfl_xor_sync(0xffffffffu, m, o));
            float s = 0.f;
#pragma unroll
            for (int j = 0; j < 32; j++) { vreg[j] = fexp(vreg[j] - m); s += vreg[j]; }
#pragma unroll
            for (int o = 16; o > 0; o >>= 1) s += __shfl_xor_sync(0xffffffffu, s, o);
            float rr = 1.0f / s;
            float* gout = attn1 + ((size_t)bh * 1024 + qbase + q) * 1024;
            const float* a2g = attn2 + ((size_t)bh * 1024 + qbase + q) * 1024;
            const float* cg  = Cmask + ((size_t)b * 1024 + qbase + q) * 1024;
#pragma unroll
            for (int j = 0; j < 32; j++) {
                int k = lane + 32 * j;
                float e = vreg[j] * rr;
                gout[k] = e;
                row[k] = cg[k] * (e - lam * a2g[k]);
            }
        }
    }
    __syncthreads();

    // ---------------- phase 2: ctx = P @ V, distance-3 ---------------------
    {
        const uint32_t ua = (uint32_t)((((lane & 15) * 2 +
                             ((lane >> 4) ^ (((lane & 15) >> 2) & 1)))) << 4);
        float cacc[4] = {0.f, 0.f, 0.f, 0.f};
        for (int ch = 0; ch < 16; ch++) {
            {
                uint32_t* Pchi = (uint32_t*)(smc + OFF_PC + (ch & 1) * 2048u);
#pragma unroll
                for (int i = 0; i < 2; i++) {
                    int pidx = tid + i * 256;
                    int q  = pidx >> 5;
                    int kp = pidx & 31;
                    int kl = kp * 2;
                    uint32_t hv = pack2h(S[q * SD + ch * 64 + kl],
                                         S[q * SD + ch * 64 + kl + 1]);
                    int kb16  = kl >> 4;
                    int colin = kl & 15;
                    int half  = colin >> 3;
                    int w     = (colin & 7) >> 1;
                    int u     = q * 2 + (half ^ ((q >> 2) & 1));
                    Pchi[kb16 * 128 + u * 4 + w] = hv;
                }
            }
            if (ch < 13) { CPWAITG2; } else { CPWAIT0; }
            __syncthreads();
            if (ch < 13) stage_kv(smb, gVh, bh, ch + 3, (ch + 3) & 3, tid);

            const uint32_t VU  = smb + OFF_KV + (uint32_t)(ch & 3) * 8192u;
            const uint32_t PbU = smb + OFF_PC + (uint32_t)(ch & 1) * 2048u;
#pragma unroll
            for (int k2 = 0; k2 < 2; k2++) {
                int lrow = k2 * 32 + (lane >> 3) * 8 + (lane & 7);
                uint32_t boff = lrow * 128 + ((wid ^ (lrow & 7)) << 4);
                uint32_t bhf[4];
                ldm_x4_t(bhf, VU + boff);
#pragma unroll
                for (int sub = 0; sub < 2; sub++) {
                    int kb16 = k2 * 2 + sub;
                    uint32_t ah[4];
                    ldm_x4(ah, PbU + kb16 * 512 + ua);
                    mma16816(cacc, ah, &bhf[sub * 2]);
                }
            }
        }
        size_t base = ((size_t)(b * 1024 + qbase + r)) * 1024 + h * 64 + wid * 8 + c2;
        float2 v0; v0.x = cacc[0]; v0.y = cacc[1];
        float2 v1; v1.x = cacc[2]; v1.y = cacc[3];
        *(float2*)&gCtx[base]            = v0;
        *(float2*)&gCtx[base + 8 * 1024] = v1;
    }
#undef SCORE_PASS
}

// ---------------------------------------------------------------------------
// stats: two-stage GroupNorm stats -> folded per-(b,d) scale/bias
// (512-block stats_part: verified 10.5 -> 8.5 us)
// ---------------------------------------------------------------------------
__global__ void stats_part(void)
{
    const int idx = blockIdx.x;          // 0..511
    const int bh = idx >> 3, eighth = idx & 7;
    const int b = bh >> 4, h = bh & 15;
    const int tid = threadIdx.x;
    __shared__ float rs[256], rq[256];
    float s = 0.f, sq = 0.f;
    for (int t = tid; t < 8192; t += 256) {
        int srow = eighth * 128 + (t >> 6), d = t & 63;
        float x = gCtx[((size_t)b * 1024 + srow) * 1024 + h * 64 + d];
        s += x; sq += x * x;
    }
    rs[tid] = s; rq[tid] = sq;
    __syncthreads();
    for (int o = 128; o > 0; o >>= 1) {
        if (tid < o) { rs[tid] += rs[tid + o]; rq[tid] += rq[tid + o]; }
        __syncthreads();
    }
    if (tid == 0) { gPartS[idx] = rs[0]; gPartQ[idx] = rq[0]; }
}

__global__ void stats_fin(const float* __restrict__ gnw,
                          const float* __restrict__ gnb)
{
    const int bh = blockIdx.x;
    const int b = bh >> 4, h = bh & 15;
    const int d0 = threadIdx.x;          // 0..63
    float s = 0.f, sq = 0.f;
#pragma unroll
    for (int i = 0; i < 8; i++) { s += gPartS[bh * 8 + i]; sq += gPartQ[bh * 8 + i]; }
    float mean = s * (1.0f / 65536.0f);
    float var  = sq * (1.0f / 65536.0f) - mean * mean;
    float rstd = rsqrtf(var + 1e-5f);
    int d = h * 64 + d0;
    float w = gnw[d];
    gScaleArr[b * 1024 + d] = rstd * w * 0.19999999999999996f;
    gBiasArr [b * 1024 + d] = (gnb[d] - mean * rstd * w) * 0.19999999999999996f;
}

// ---------------------------------------------------------------------------
// Launch
// ---------------------------------------------------------------------------
extern "C" void kernel_launch(void* const* d_in, const int* in_sizes, int n_in,
                              void* d_out, int out_size)
{
    const float* x    = (const float*)d_in[0];
    const float* lam  = (const float*)d_in[1];
    const float* C    = (const float*)d_in[2];
    const int*   pad  = (const int*)  d_in[3];
    const float* wq   = (const float*)d_in[4];
    const float* wqb  = (const float*)d_in[5];
    const float* wk   = (const float*)d_in[6];
    const float* wkb  = (const float*)d_in[7];
    const float* wv   = (const float*)d_in[8];
    const float* wvb  = (const float*)d_in[9];
    const float* wo   = (const float*)d_in[10];
    const float* wob  = (const float*)d_in[11];
    const float* gnw  = (const float*)d_in[12];
    const float* gnb  = (const float*)d_in[13];

    float* out   = (float*)d_out;
    float* attn1 = out + (size_t)BB * SS * DD;
    float* attn2 = attn1 + (size_t)BB * HH * SS * SS;

    cudaFuncSetAttribute(attn_kernel, cudaFuncAttributeMaxDynamicSharedMemorySize,
                         ATTN_SMEM);
    cudaFuncSetAttribute(mma_gemm<0>, cudaFuncAttributeMaxDynamicSharedMemorySize, 65536);
    cudaFuncSetAttribute(mma_gemm<1>, cudaFuncAttributeMaxDynamicSharedMemorySize, 65536);

    prep_all<<<512, 256>>>(x, wq, wk, wv, wo);
    mma_gemm<0><<<dim3(40, 32), 256, 65536>>>(wqb, wkb, wvb, nullptr, nullptr);
    attn_kernel<<<dim3(64, 16, 4), 256, ATTN_SMEM>>>(C, pad, lam, attn1, attn2);
    stats_part<<<512, 256>>>();
    stats_fin<<<64, 64>>>(gnw, gnb);
    prep_ctx<<<512, 256>>>();
    mma_gemm<1><<<dim3(8, 32), 256, 65536>>>(nullptr, nullptr, nullptr, wob, out);
}

// round 17
// speedup vs baseline: 1.0363x; 1.0003x over previous
#include <cuda_runtime.h>
#include <cuda_fp16.h>
#include <cstdint>

// Problem constants
#define BB 4
#define SS 1024
#define DD 1024
#define HH 16
#define DH 64

// ===========================================================================
// Packed fp16 device globals (uint32 = half2 pair along k/dh), all hi-only.
// ===========================================================================
__device__ __align__(16) uint32_t gXh[2097152];                  // x      [4096][512]
__device__ __align__(16) uint32_t gWh[2621440];                  // wq|wk|wv [5120][512]
__device__ __align__(16) uint32_t gWoh[524288];                  // wo     [1024][512]
__device__ __align__(16) uint32_t gAh[2097152];                  // normalized ctx
__device__ __align__(16) uint32_t gQ1h[2097152];
__device__ __align__(16) uint32_t gQ2h[2097152];
__device__ __align__(16) uint32_t gK1h[2097152];
__device__ __align__(16) uint32_t gK2h[2097152];
__device__ __align__(16) uint32_t gVh [2097152];
__device__ float gCtx[4194304];
__device__ float gScaleArr[4096];
__device__ float gBiasArr [4096];
__device__ float gPartS[512], gPartQ[512];

// ===========================================================================
// helpers
// ===========================================================================
static __device__ __forceinline__ uint32_t smem_u32(const void* p) {
    uint32_t a;
    asm("{ .reg .u64 t; cvta.to.shared.u64 t, %1; cvt.u32.u64 %0, t; }"
        : "=r"(a) : "l"(p));
    return a;
}
static __device__ __forceinline__ void ldm_x4(uint32_t* r, uint32_t addr) {
    asm volatile("ldmatrix.sync.aligned.m8n8.x4.shared.b16 {%0,%1,%2,%3}, [%4];"
                 : "=r"(r[0]), "=r"(r[1]), "=r"(r[2]), "=r"(r[3]) : "r"(addr));
}
static __device__ __forceinline__ void ldm_x2(uint32_t* r, uint32_t addr) {
    asm volatile("ldmatrix.sync.aligned.m8n8.x2.shared.b16 {%0,%1}, [%2];"
                 : "=r"(r[0]), "=r"(r[1]) : "r"(addr));
}
static __device__ __forceinline__ void ldm_x4_t(uint32_t* r, uint32_t addr) {
    asm volatile("ldmatrix.sync.aligned.m8n8.x4.trans.shared.b16 {%0,%1,%2,%3}, [%4];"
                 : "=r"(r[0]), "=r"(r[1]), "=r"(r[2]), "=r"(r[3]) : "r"(addr));
}
// fp16 mma, fp32 accumulate
static __device__ __forceinline__ void mma16816(float* c, const uint32_t* a,
                                                const uint32_t* b) {
    asm volatile(
        "mma.sync.aligned.m16n8k16.row.col.f32.f16.f16.f32 "
        "{%0,%1,%2,%3}, {%4,%5,%6,%7}, {%8,%9}, {%0,%1,%2,%3};"
        : "+f"(c[0]), "+f"(c[1]), "+f"(c[2]), "+f"(c[3])
        : "r"(a[0]), "r"(a[1]), "r"(a[2]), "r"(a[3]), "r"(b[0]), "r"(b[1]));
}
static __device__ __forceinline__ uint32_t pack2h(float f0, float f1) {
    __half2 hp; hp.x = __float2half_rn(f0); hp.y = __float2half_rn(f1);
    return *reinterpret_cast<uint32_t*>(&hp);
}
// fast exp on the FMA pipe
static __device__ __forceinline__ float fexp(float x) {
    float t = x * 1.4426950408889634f;
    t = fmaxf(t, -126.0f);
    float fl = floorf(t);
    float f = t - fl;
    float p = 1.33335581e-3f;
    p = fmaf(p, f, 9.61812910e-3f);
    p = fmaf(p, f, 5.55041087e-2f);
    p = fmaf(p, f, 2.40226507e-1f);
    p = fmaf(p, f, 6.93147180e-1f);
    p = fmaf(p, f, 1.0f);
    return p * __int_as_float(((int)fl + 127) << 23);
}
static __device__ __forceinline__ uint32_t sw_off(int row, int chunk) {
    return (uint32_t)(row * 64 + ((chunk ^ ((row >> 1) & 3)) << 4));
}
#define CPA16(dst, src) \
    asm volatile("cp.async.cg.shared.global [%0], [%1], 16;" :: "r"(dst), "l"(src))
#define CPCOMMIT asm volatile("cp.async.commit_group;" ::: "memory")
#define CPWAITG3 asm volatile("cp.async.wait_group 3;" ::: "memory")
#define CPWAIT0  asm volatile("cp.async.wait_group 0;" ::: "memory")

// ===========================================================================
// prep_all: fp32 -> fp16 hi-only conversions.
// ===========================================================================
__global__ void prep_all(const float* __restrict__ x,
                         const float* __restrict__ wq,
                         const float* __restrict__ wk,
                         const float* __restrict__ wv,
                         const float* __restrict__ wo)
{
    int i = blockIdx.x * blockDim.x + threadIdx.x;
    int stride = gridDim.x * blockDim.x;
    for (; i < 5242880; i += stride) {
        const float* src; uint32_t* dh; int j;
        if (i < 2097152)      { j = i;           src = x;  dh = gXh; }
        else if (i < 3145728) { j = i - 2097152; src = wq; dh = gWh; }
        else if (i < 4194304) { j = i - 3145728; src = wk; dh = gWh + 1048576; }
        else if (i < 4718592) { j = i - 4194304; src = wv; dh = gWh + 2097152; }
        else                  { j = i - 4718592; src = wo; dh = gWoh; }
        float2 v = *(const float2*)(src + 2 * (size_t)j);
        dh[j] = pack2h(v.x, v.y);
    }
}

// prep_ctx: gAh = fp16(gCtx * scale + bias)
__global__ void prep_ctx()
{
    int i = blockIdx.x * blockDim.x + threadIdx.x;
    int stride = gridDim.x * blockDim.x;
    for (; i < 2097152; i += stride) {
        int m = i >> 9, kp = i & 511, b = m >> 10;
        float2 v  = *(const float2*)&gCtx[(size_t)m * 1024 + 2 * kp];
        float2 sc = *(const float2*)&gScaleArr[b * 1024 + 2 * kp];
        float2 bi = *(const float2*)&gBiasArr [b * 1024 + 2 * kp];
        gAh[i] = pack2h(v.x * sc.x + bi.x, v.y * sc.y + bi.y);
    }
}

// ===========================================================================
// mma_gemm<MODE>: fp16 1-pass GEMM, 128x128 tile, BK=32,
// 5-buffer distance-4 cp.async pipeline. smem: 5 x (A 8K | B 8K) = 80KB.
// ===========================================================================
template<int MODE>
__global__ __launch_bounds__(256, 2)
void mma_gemm(const float* __restrict__ wqb, const float* __restrict__ wkb,
              const float* __restrict__ wvb, const float* __restrict__ ob,
              float* __restrict__ out)
{
    extern __shared__ char sm[];
    const uint32_t smb = smem_u32(sm);
    const int tid  = threadIdx.x;
    const int lane = tid & 31;
    const int warp = tid >> 5;
    const int wm   = warp >> 1;
    const int wn   = warp & 1;
    const int n0 = blockIdx.x * 128;
    const int m0 = blockIdx.y * 128;
    const int b  = m0 >> 10;

    const uint32_t* Ah = (MODE == 0) ? gXh : gAh;
    const uint32_t* Bh = (MODE == 0) ? gWh : gWoh;
    const float* Wb;
    if (MODE == 0) {
        if (n0 < 2048)      Wb = wqb + n0;
        else if (n0 < 4096) Wb = wkb + (n0 - 2048);
        else                Wb = wvb + (n0 - 4096);
    } else {
        Wb = ob + n0;
    }

    float acc[2][8][4];
#pragma unroll
    for (int i = 0; i < 2; i++)
#pragma unroll
        for (int j = 0; j < 8; j++)
#pragma unroll
            for (int v = 0; v < 4; v++) acc[i][j][v] = 0.f;

#define STAGE_GEMM(c, buf)                                                        \
    {                                                                             \
        _Pragma("unroll")                                                         \
        for (int i = 0; i < 4; i++) {                                             \
            int t = tid + i * 256;                                                \
            int tile = t >> 9;                                                    \
            int r = (t >> 2) & 127;                                               \
            int u = t & 3;                                                        \
            uint32_t dst = smb + (uint32_t)(buf) * 16384u + tile * 8192u          \
                           + sw_off(r, u);                                        \
            const uint32_t* sa = (tile == 0) ? Ah : Bh;                           \
            const uint32_t* src = sa + (size_t)((tile == 0 ? m0 : n0) + r) * 512  \
                                   + (c) * 16 + u * 4;                            \
            CPA16(dst, src);                                                      \
        }                                                                         \
        CPCOMMIT;                                                                 \
    }

    STAGE_GEMM(0, 0);
    STAGE_GEMM(1, 1);
    STAGE_GEMM(2, 2);
    STAGE_GEMM(3, 3);
    int bufc = 0, sbuf = 4;
    for (int c = 0; c < 32; c++) {
        if (c < 28) { CPWAITG3; } else { CPWAIT0; }
        __syncthreads();
        if (c < 28) {
            STAGE_GEMM(c + 4, sbuf);
            sbuf++; if (sbuf >= 5) sbuf = 0;
        }

        const uint32_t base = smb + (uint32_t)bufc * 16384u;
        const uint32_t AhU = base;
        const uint32_t BhiU = base + 8192u;
#pragma unroll
        for (int kk = 0; kk < 2; kk++) {
            uint32_t ah[2][4];
            const int arow = wm * 32 + (lane & 7) + (((lane >> 3) & 1) << 3);
            const int achunk = kk * 2 + (lane >> 4);
#pragma unroll
            for (int mi = 0; mi < 2; mi++)
                ldm_x4(ah[mi], AhU + sw_off(arow + mi * 16, achunk));
            const int brow0 = wn * 64 + (lane & 7) + ((lane >> 4) << 3);
            const int bchunk = kk * 2 + ((lane >> 3) & 1);
#pragma unroll
            for (int half = 0; half < 2; half++) {
                uint32_t bhf[2][4];
#pragma unroll
                for (int j = 0; j < 2; j++)
                    ldm_x4(bhf[j], BhiU + sw_off(brow0 + half * 32 + j * 16, bchunk));
#pragma unroll
                for (int mi = 0; mi < 2; mi++)
#pragma unroll
                    for (int j = 0; j < 2; j++)
#pragma unroll
                        for (int s = 0; s < 2; s++)
                            mma16816(acc[mi][half * 4 + j * 2 + s],
                                     ah[mi], &bhf[j][s * 2]);
            }
        }
        bufc++; if (bufc >= 5) bufc = 0;
    }
#undef STAGE_GEMM

    if (MODE == 0) {
        const int sect = n0 >> 10;
        uint32_t* dstH = (sect == 0) ? gQ1h : (sect == 1) ? gQ2h :
                         (sect == 2) ? gK1h : (sect == 3) ? gK2h : gVh;
#pragma unroll
        for (int mi = 0; mi < 2; mi++) {
            int m = m0 + wm * 32 + mi * 16 + (lane >> 2);
            int s = m & 1023;
#pragma unroll
            for (int nh = 0; nh < 8; nh++) {
                int nl = wn * 64 + nh * 8 + 2 * (lane & 3);
                int nn = (n0 & 1023) + nl;
                int h = nn >> 6, dh = nn & 63;
                float b0 = Wb[nl], b1 = Wb[nl + 1];
                size_t base = ((size_t)((b << 4) + h) * 1024 + s) * 32 + (dh >> 1);
                dstH[base]       = pack2h(acc[mi][nh][0] + b0, acc[mi][nh][1] + b1);
                dstH[base + 256] = pack2h(acc[mi][nh][2] + b0, acc[mi][nh][3] + b1);
            }
        }
    } else {
#pragma unroll
        for (int mi = 0; mi < 2; mi++) {
            int m = m0 + wm * 32 + mi * 16 + (lane >> 2);
#pragma unroll
            for (int nh = 0; nh < 8; nh++) {
                int nl = wn * 64 + nh * 8 + 2 * (lane & 3);
                float b0 = Wb[nl], b1 = Wb[nl + 1];
                float2 v0; v0.x = acc[mi][nh][0] + b0; v0.y = acc[mi][nh][1] + b1;
                float2 v1; v1.x = acc[mi][nh][2] + b0; v1.y = acc[mi][nh][3] + b1;
                *(float2*)&out[(size_t)m * 1024 + n0 + nl]       = v0;
                *(float2*)&out[(size_t)(m + 8) * 1024 + n0 + nl] = v1;
            }
        }
    }
}

// ===========================================================================
// attn_kernel: qt=16, 256 thr, occ 2. K/V hi-only, 5-buffer distance-4.
// smem: S fp32[16][1032] (66048) | KV 5x8KB (40960) | Pc 2x2KB (4096)
// ===========================================================================
#define SD 1032
#define OFF_KV 66048u
#define OFF_PC 107008u
#define ATTN_SMEM 111104

static __device__ __forceinline__ void stage_kv(uint32_t smb, const uint32_t* sH,
                                                int bh, int ch64, int buf, int tid)
{
#pragma unroll
    for (int i = 0; i < 2; i++) {
        int t = tid + i * 256;            // 0..511
        int row = t >> 3;                 // 0..63
        int cu = t & 7;
        uint32_t dst = smb + OFF_KV + buf * 8192u +
                       row * 128u + (uint32_t)((cu ^ (row & 7)) << 4);
        const uint32_t* src = sH + ((size_t)bh * 1024 + ch64 * 64 + row) * 32 + cu * 4;
        CPA16(dst, src);
    }
    CPCOMMIT;
}

__global__ __launch_bounds__(256, 2)
void attn_kernel(const float* __restrict__ Cmask,
                 const int*   __restrict__ pad,
                 const float* __restrict__ lamp,
                 float* __restrict__ attn1,
                 float* __restrict__ attn2)
{
    extern __shared__ char smc[];
    const uint32_t smb = smem_u32(smc);
    float* S = (float*)smc;

    const int qt = blockIdx.x;
    const int h  = blockIdx.y;
    const int b  = blockIdx.z;
    const int tid  = threadIdx.x;
    const int wid  = tid >> 5;
    const int lane = tid & 31;
    const int bh = b * 16 + h;
    const int qbase = qt * 16;
    const int r  = lane >> 2;
    const int c2 = (lane & 3) * 2;
    const int* padrow = pad + b * 1024;

    // score pass, 5-buffer distance-4; caller staged chunks 0..3 of KH.
#define SCORE_PASS(KH, QH)                                                       \
    {                                                                            \
        uint32_t qh[4][4];                                                       \
        {                                                                        \
            size_t qb0 = ((size_t)bh * 1024 + qbase + r) * 32;                   \
            size_t qb1 = qb0 + 8 * 32;                                           \
            _Pragma("unroll")                                                    \
            for (int kk = 0; kk < 4; kk++) {                                     \
                int p = kk * 8 + (lane & 3);                                     \
                qh[kk][0] = QH[qb0 + p];                                         \
                qh[kk][1] = QH[qb1 + p];                                         \
                qh[kk][2] = QH[qb0 + p + 4];                                     \
                qh[kk][3] = QH[qb1 + p + 4];                                     \
            }                                                                    \
        }                                                                        \
        int bufc = 0, sbuf = 4;                                                  \
        for (int ch = 0; ch < 16; ch++) {                                        \
            if (ch < 12) { CPWAITG3; } else { CPWAIT0; }                         \
            __syncthreads();                                                     \
            if (ch < 12) {                                                       \
                stage_kv(smb, KH, bh, ch + 4, sbuf, tid);                        \
                sbuf++; if (sbuf >= 5) sbuf = 0;                                 \
            }                                                                    \
            const uint32_t KU = smb + OFF_KV + (uint32_t)bufc * 8192u;           \
            float c0[4] = {0.f, 0.f, 0.f, 0.f};                                  \
            const int brow = wid * 8 + (lane & 7);                               \
            _Pragma("unroll")                                                    \
            for (int kk = 0; kk < 4; kk++) {                                     \
                int bch = kk * 2 + ((lane >> 3) & 1);                            \
                uint32_t off = brow * 128 + ((bch ^ (brow & 7)) << 4);           \
                uint32_t bhf[2];                                                 \
                ldm_x2(bhf, KU + off);                                           \
                mma16816(c0, qh[kk], bhf);                                       \
            }                                                                    \
            const int col = ch * 64 + wid * 8 + c2;                              \
            float2 v;                                                            \
            v.x = c0[0] * 0.125f; v.y = c0[1] * 0.125f;                          \
            *(float2*)&S[r * SD + col] = v;                                      \
            v.x = c0[2] * 0.125f; v.y = c0[3] * 0.125f;                          \
            *(float2*)&S[(r + 8) * SD + col] = v;                                \
            bufc++; if (bufc >= 5) bufc = 0;                                     \
        }                                                                        \
    }

    // ---------------- variant 2 scores -> softmax -> attn2 ----------------
    stage_kv(smb, gK2h, bh, 0, 0, tid);
    stage_kv(smb, gK2h, bh, 1, 1, tid);
    stage_kv(smb, gK2h, bh, 2, 2, tid);
    stage_kv(smb, gK2h, bh, 3, 3, tid);
    SCORE_PASS(gK2h, gQ2h);

    // prefetch K1 chunks 0..3 during softmax (4 groups outstanding)
    stage_kv(smb, gK1h, bh, 0, 0, tid);
    stage_kv(smb, gK1h, bh, 1, 1, tid);
    stage_kv(smb, gK1h, bh, 2, 2, tid);
    stage_kv(smb, gK1h, bh, 3, 3, tid);
    __syncthreads();

    for (int q = wid; q < 16; q += 8) {
        float* row = S + q * SD;
        float vreg[32];
        float m = -3.4e38f;
#pragma unroll
        for (int j = 0; j < 32; j++) {
            int k = lane + 32 * j;
            float v = row[k];
            if (padrow[k] == 0) v = -1e9f;
            vreg[j] = v;
            m = fmaxf(m, v);
        }
#pragma unroll
        for (int o = 16; o > 0; o >>= 1) m = fmaxf(m, __shfl_xor_sync(0xffffffffu, m, o));
        float s = 0.f;
#pragma unroll
        for (int j = 0; j < 32; j++) { vreg[j] = fexp(vreg[j] - m); s += vreg[j]; }
#pragma unroll
        for (int o = 16; o > 0; o >>= 1) s += __shfl_xor_sync(0xffffffffu, s, o);
        float rr = 1.0f / s;
        float* gout = attn2 + ((size_t)bh * 1024 + qbase + q) * 1024;
#pragma unroll
        for (int j = 0; j < 32; j++)
            gout[lane + 32 * j] = vreg[j] * rr;
    }
    __syncthreads();

    // ---------------- variant 1 scores -> softmax+combine -> attn1 & P in S -
    SCORE_PASS(gK1h, gQ1h);

    // prefetch V chunks 0..3 during softmax
    stage_kv(smb, gVh, bh, 0, 0, tid);
    stage_kv(smb, gVh, bh, 1, 1, tid);
    stage_kv(smb, gVh, bh, 2, 2, tid);
    stage_kv(smb, gVh, bh, 3, 3, tid);
    __syncthreads();

    {
        const float lam = lamp[0];
        for (int q = wid; q < 16; q += 8) {
            float* row = S + q * SD;
            float vreg[32];
            float m = -3.4e38f;
#pragma unroll
            for (int j = 0; j < 32; j++) {
                int k = lane + 32 * j;
                float v = row[k];
                if (padrow[k] == 0) v = -1e9f;
                vreg[j] = v;
                m = fmaxf(m, v);
            }
#pragma unroll
            for (int o = 16; o > 0; o >>= 1) m = fmaxf(m, __shfl_xor_sync(0xffffffffu, m, o));
            float s = 0.f;
#pragma unroll
            for (int j = 0; j < 32; j++) { vreg[j] = fexp(vreg[j] - m); s += vreg[j]; }
#pragma unroll
            for (int o = 16; o > 0; o >>= 1) s += __shfl_xor_sync(0xffffffffu, s, o);
            float rr = 1.0f / s;
            float* gout = attn1 + ((size_t)bh * 1024 + qbase + q) * 1024;
            const float* a2g = attn2 + ((size_t)bh * 1024 + qbase + q) * 1024;
            const float* cg  = Cmask + ((size_t)b * 1024 + qbase + q) * 1024;
#pragma unroll
            for (int j = 0; j < 32; j++) {
                int k = lane + 32 * j;
                float e = vreg[j] * rr;
                gout[k] = e;
                row[k] = cg[k] * (e - lam * a2g[k]);
            }
        }
    }
    __syncthreads();

    // ---------------- phase 2: ctx = P @ V, 5-buffer distance-4 ------------
    {
        const uint32_t ua = (uint32_t)((((lane & 15) * 2 +
                             ((lane >> 4) ^ (((lane & 15) >> 2) & 1)))) << 4);
        float cacc[4] = {0.f, 0.f, 0.f, 0.f};
        int bufc = 0, sbuf = 4;
        for (int ch = 0; ch < 16; ch++) {
            {
                uint32_t* Pchi = (uint32_t*)(smc + OFF_PC + (ch & 1) * 2048u);
#pragma unroll
                for (int i = 0; i < 2; i++) {
                    int pidx = tid + i * 256;
                    int q  = pidx >> 5;
                    int kp = pidx & 31;
                    int kl = kp * 2;
                    uint32_t hv = pack2h(S[q * SD + ch * 64 + kl],
                                         S[q * SD + ch * 64 + kl + 1]);
                    int kb16  = kl >> 4;
                    int colin = kl & 15;
                    int half  = colin >> 3;
                    int w     = (colin & 7) >> 1;
                    int u     = q * 2 + (half ^ ((q >> 2) & 1));
                    Pchi[kb16 * 128 + u * 4 + w] = hv;
                }
            }
            if (ch < 12) { CPWAITG3; } else { CPWAIT0; }
            __syncthreads();
            if (ch < 12) {
                stage_kv(smb, gVh, bh, ch + 4, sbuf, tid);
                sbuf++; if (sbuf >= 5) sbuf = 0;
            }

            const uint32_t VU  = smb + OFF_KV + (uint32_t)bufc * 8192u;
            const uint32_t PbU = smb + OFF_PC + (uint32_t)(ch & 1) * 2048u;
#pragma unroll
            for (int k2 = 0; k2 < 2; k2++) {
                int lrow = k2 * 32 + (lane >> 3) * 8 + (lane & 7);
                uint32_t boff = lrow * 128 + ((wid ^ (lrow & 7)) << 4);
                uint32_t bhf[4];
                ldm_x4_t(bhf, VU + boff);
#pragma unroll
                for (int sub = 0; sub < 2; sub++) {
                    int kb16 = k2 * 2 + sub;
                    uint32_t ah[4];
                    ldm_x4(ah, PbU + kb16 * 512 + ua);
                    mma16816(cacc, ah, &bhf[sub * 2]);
                }
            }
            bufc++; if (bufc >= 5) bufc = 0;
        }
        size_t base = ((size_t)(b * 1024 + qbase + r)) * 1024 + h * 64 + wid * 8 + c2;
        float2 v0; v0.x = cacc[0]; v0.y = cacc[1];
        float2 v1; v1.x = cacc[2]; v1.y = cacc[3];
        *(float2*)&gCtx[base]            = v0;
        *(float2*)&gCtx[base + 8 * 1024] = v1;
    }
#undef SCORE_PASS
}

// ---------------------------------------------------------------------------
// stats: two-stage GroupNorm stats -> folded per-(b,d) scale/bias
// ---------------------------------------------------------------------------
__global__ void stats_part(void)
{
    const int idx = blockIdx.x;          // 0..511
    const int bh = idx >> 3, eighth = idx & 7;
    const int b = bh >> 4, h = bh & 15;
    const int tid = threadIdx.x;
    __shared__ float rs[256], rq[256];
    float s = 0.f, sq = 0.f;
    for (int t = tid; t < 8192; t += 256) {
        int srow = eighth * 128 + (t >> 6), d = t & 63;
        float x = gCtx[((size_t)b * 1024 + srow) * 1024 + h * 64 + d];
        s += x; sq += x * x;
    }
    rs[tid] = s; rq[tid] = sq;
    __syncthreads();
    for (int o = 128; o > 0; o >>= 1) {
        if (tid < o) { rs[tid] += rs[tid + o]; rq[tid] += rq[tid + o]; }
        __syncthreads();
    }
    if (tid == 0) { gPartS[idx] = rs[0]; gPartQ[idx] = rq[0]; }
}

__global__ void stats_fin(const float* __restrict__ gnw,
                          const float* __restrict__ gnb)
{
    const int bh = blockIdx.x;
    const int b = bh >> 4, h = bh & 15;
    const int d0 = threadIdx.x;          // 0..63
    float s = 0.f, sq = 0.f;
#pragma unroll
    for (int i = 0; i < 8; i++) { s += gPartS[bh * 8 + i]; sq += gPartQ[bh * 8 + i]; }
    float mean = s * (1.0f / 65536.0f);
    float var  = sq * (1.0f / 65536.0f) - mean * mean;
    float rstd = rsqrtf(var + 1e-5f);
    int d = h * 64 + d0;
    float w = gnw[d];
    gScaleArr[b * 1024 + d] = rstd * w * 0.19999999999999996f;
    gBiasArr [b * 1024 + d] = (gnb[d] - mean * rstd * w) * 0.19999999999999996f;
}

// ---------------------------------------------------------------------------
// Launch
// ---------------------------------------------------------------------------
extern "C" void kernel_launch(void* const* d_in, const int* in_sizes, int n_in,
                              void* d_out, int out_size)
{
    const float* x    = (const float*)d_in[0];
    const float* lam  = (const float*)d_in[1];
    const float* C    = (const float*)d_in[2];
    const int*   pad  = (const int*)  d_in[3];
    const float* wq   = (const float*)d_in[4];
    const float* wqb  = (const float*)d_in[5];
    const float* wk   = (const float*)d_in[6];
    const float* wkb  = (const float*)d_in[7];
    const float* wv   = (const float*)d_in[8];
    const float* wvb  = (const float*)d_in[9];
    const float* wo   = (const float*)d_in[10];
    const float* wob  = (const float*)d_in[11];
    const float* gnw  = (const float*)d_in[12];
    const float* gnb  = (const float*)d_in[13];

    float* out   = (float*)d_out;
    float* attn1 = out + (size_t)BB * SS * DD;
    float* attn2 = attn1 + (size_t)BB * HH * SS * SS;

    cudaFuncSetAttribute(attn_kernel, cudaFuncAttributeMaxDynamicSharedMemorySize,
                         ATTN_SMEM);
    cudaFuncSetAttribute(mma_gemm<0>, cudaFuncAttributeMaxDynamicSharedMemorySize, 81920);
    cudaFuncSetAttribute(mma_gemm<1>, cudaFuncAttributeMaxDynamicSharedMemorySize, 81920);

    prep_all<<<512, 256>>>(x, wq, wk, wv, wo);
    mma_gemm<0><<<dim3(40, 32), 256, 81920>>>(wqb, wkb, wvb, nullptr, nullptr);
    attn_kernel<<<dim3(64, 16, 4), 256, ATTN_SMEM>>>(C, pad, lam, attn1, attn2);
    stats_part<<<512, 256>>>();
    stats_fin<<<64, 64>>>(gnw, gnb);
    prep_ctx<<<512, 256>>>();
    mma_gemm<1><<<dim3(8, 32), 256, 81920>>>(nullptr, nullptr, nullptr, wob, out);
}